// round 13
// baseline (speedup 1.0000x reference)
#include <cuda_runtime.h>
#include <cuda_bf16.h>
#include <cstdint>

#define BB 2
#define TT 2048
#define CC 2048
#define HH 16
#define DD 128
#define MTOT (BB * TT)
#define KTOT CC
#define NQKV 2304
#define QSCALE (0.08838834764831845f * 1.44269504088896340f)
#define QMAX 31000.0f

typedef __nv_bfloat16 bf16;

__device__ bf16 g_xh[(size_t)MTOT * CC],  g_xl[(size_t)MTOT * CC];
__device__ bf16 g_wh[(size_t)KTOT * NQKV], g_wl[(size_t)KTOT * NQKV];
__device__ float g_bias[NQKV];
__device__ int8_t g_woTa[(size_t)CC * KTOT], g_woTb[(size_t)CC * KTOT];  // [n][k]
__device__ int8_t g_Oa[(size_t)MTOT * CC],   g_Ob[(size_t)MTOT * CC];    // [m][k]
__device__ unsigned g_amax[2];   // 0 = |wo|max, 1 = |O|max

__device__ bf16 g_Qh[(size_t)MTOT * CC],  g_Ql[(size_t)MTOT * CC];
__device__ bf16 g_Kh[(size_t)MTOT * DD],  g_Kl[(size_t)MTOT * DD];
__device__ bf16 g_Vh[(size_t)MTOT * DD],  g_Vl[(size_t)MTOT * DD];
__device__ bf16 g_Oh[(size_t)MTOT * CC],  g_Ol[(size_t)MTOT * CC];

__device__ __forceinline__ uint32_t smem_u32(const void* p) {
    uint32_t a;
    asm("{ .reg .u64 t; cvta.to.shared.u64 t, %1; cvt.u32.u64 %0, t; }"
        : "=r"(a) : "l"(p));
    return a;
}
__device__ __forceinline__ float ex2(float x) {
    float y; asm("ex2.approx.ftz.f32 %0, %1;" : "=f"(y) : "f"(x)); return y;
}

#define LDSM_X4(r0, r1, r2, r3, addr) \
    asm volatile("ldmatrix.sync.aligned.m8n8.x4.shared.b16 {%0,%1,%2,%3}, [%4];" \
                 : "=r"(r0), "=r"(r1), "=r"(r2), "=r"(r3) : "r"(addr))
#define LDSM_X4_T(r0, r1, r2, r3, addr) \
    asm volatile("ldmatrix.sync.aligned.m8n8.x4.trans.shared.b16 {%0,%1,%2,%3}, [%4];" \
                 : "=r"(r0), "=r"(r1), "=r"(r2), "=r"(r3) : "r"(addr))
#define MMA_BF16(d, a, b0v, b1v) \
    asm volatile("mma.sync.aligned.m16n8k16.row.col.f32.bf16.bf16.f32 " \
                 "{%0,%1,%2,%3}, {%4,%5,%6,%7}, {%8,%9}, {%0,%1,%2,%3};" \
                 : "+f"((d)[0]), "+f"((d)[1]), "+f"((d)[2]), "+f"((d)[3]) \
                 : "r"((a)[0]), "r"((a)[1]), "r"((a)[2]), "r"((a)[3]), \
                   "r"(b0v), "r"(b1v))
#define MMA_S8(d, a, b0v, b1v) \
    asm volatile("mma.sync.aligned.m16n8k32.row.col.s32.s8.s8.s32 " \
                 "{%0,%1,%2,%3}, {%4,%5,%6,%7}, {%8,%9}, {%0,%1,%2,%3};" \
                 : "+r"((d)[0]), "+r"((d)[1]), "+r"((d)[2]), "+r"((d)[3]) \
                 : "r"((a)[0]), "r"((a)[1]), "r"((a)[2]), "r"((a)[3]), \
                   "r"(b0v), "r"(b1v))
#define CP16(dst, src) \
    asm volatile("cp.async.cg.shared.global [%0], [%1], 16;" :: "r"(dst), "l"(src))
#define CP_COMMIT() asm volatile("cp.async.commit_group;" ::: "memory")
#define CP_WAIT(n)  asm volatile("cp.async.wait_group %0;" :: "n"(n) : "memory")

__device__ __forceinline__ uint32_t pack_bf2(bf16 a, bf16 b) {
    return ((uint32_t)__bfloat16_as_ushort(b) << 16) | (uint32_t)__bfloat16_as_ushort(a);
}
__device__ __forceinline__ void split2(float x, float y, uint32_t& hi, uint32_t& lo) {
    bf16 hx = __float2bfloat16(x), hy = __float2bfloat16(y);
    hi = pack_bf2(hx, hy);
    lo = pack_bf2(__float2bfloat16(x - __bfloat162float(hx)),
                  __float2bfloat16(y - __bfloat162float(hy)));
}
__device__ __forceinline__ void qdig(float v, float S, int& h, int& l) {
    int q = __float2int_rn(v * S);
    h = (q + 128) >> 8;
    l = q - (h << 8);
}

__global__ void zero_amax() { if (threadIdx.x < 2) g_amax[threadIdx.x] = 0u; }

__global__ __launch_bounds__(256) void amax_wo(const float* __restrict__ wo)
{
    __shared__ float wmax[8];
    int tid = threadIdx.x;
    float m = 0.f;
#pragma unroll
    for (int p = 0; p < 4; p++) {
        float4 v = ((const float4*)wo)[blockIdx.x * 1024 + p * 256 + tid];
        m = fmaxf(m, fmaxf(fmaxf(fabsf(v.x), fabsf(v.y)),
                           fmaxf(fabsf(v.z), fabsf(v.w))));
    }
#pragma unroll
    for (int o = 16; o > 0; o >>= 1)
        m = fmaxf(m, __shfl_xor_sync(0xffffffffu, m, o));
    if ((tid & 31) == 0) wmax[tid >> 5] = m;
    __syncthreads();
    if (tid == 0) {
        float bm = wmax[0];
#pragma unroll
        for (int i = 1; i < 8; i++) bm = fmaxf(bm, wmax[i]);
        atomicMax(&g_amax[0], __float_as_uint(bm));
    }
}

// prep: x/wq/wk/wv -> bf16 hi/lo; wo -> transposed s8 digits; bias pack.
__global__ __launch_bounds__(256) void prep_kernel(
    const float* __restrict__ x,  const float* __restrict__ wq,
    const float* __restrict__ wk, const float* __restrict__ wv,
    const float* __restrict__ wo,
    const float* __restrict__ qb, const float* __restrict__ kb,
    const float* __restrict__ vb)
{
    int blk = blockIdx.x, tid = threadIdx.x;
    if (blk < 8192) {
        int i = blk * 256 + tid;
        float4 v = ((const float4*)x)[i];
        uint32_t h0, l0, h1, l1;
        split2(v.x, v.y, h0, l0); split2(v.z, v.w, h1, l1);
        ((uint2*)g_xh)[i] = make_uint2(h0, h1);
        ((uint2*)g_xl)[i] = make_uint2(l0, l1);
    } else if (blk < 12288) {
        int i = (blk - 8192) * 256 + tid;
        int row = i >> 9, col = (i << 2) & 2047;
        float4 v = ((const float4*)wq)[i];
        uint32_t h0, l0, h1, l1;
        split2(v.x, v.y, h0, l0); split2(v.z, v.w, h1, l1);
        size_t o = (size_t)row * NQKV + col;
        *(uint2*)(g_wh + o) = make_uint2(h0, h1);
        *(uint2*)(g_wl + o) = make_uint2(l0, l1);
    } else if (blk < 12544) {
        int i = (blk - 12288) * 256 + tid;
        int row = i >> 5, col = (i << 2) & 127;
        float4 v = ((const float4*)wk)[i];
        uint32_t h0, l0, h1, l1;
        split2(v.x, v.y, h0, l0); split2(v.z, v.w, h1, l1);
        size_t o = (size_t)row * NQKV + 2048 + col;
        *(uint2*)(g_wh + o) = make_uint2(h0, h1);
        *(uint2*)(g_wl + o) = make_uint2(l0, l1);
    } else if (blk < 12800) {
        int i = (blk - 12544) * 256 + tid;
        int row = i >> 5, col = (i << 2) & 127;
        float4 v = ((const float4*)wv)[i];
        uint32_t h0, l0, h1, l1;
        split2(v.x, v.y, h0, l0); split2(v.z, v.w, h1, l1);
        size_t o = (size_t)row * NQKV + 2176 + col;
        *(uint2*)(g_wh + o) = make_uint2(h0, h1);
        *(uint2*)(g_wl + o) = make_uint2(l0, l1);
    } else if (blk < 16896) {
        float S = QMAX / __uint_as_float(g_amax[0]);
        int j = (blk - 12800) * 256 + tid;
        int n = j & 2047;
        int k4 = (j >> 11) * 4;
        uint32_t ha = 0, la = 0;
#pragma unroll
        for (int r = 0; r < 4; r++) {
            float v = wo[(size_t)(k4 + r) * CC + n];
            int h, l;
            qdig(v, S, h, l);
            ha |= (uint32_t)(h & 0xff) << (8 * r);
            la |= (uint32_t)(l & 0xff) << (8 * r);
        }
        size_t o = ((size_t)n * KTOT + k4) >> 2;
        ((uint32_t*)g_woTa)[o] = ha;
        ((uint32_t*)g_woTb)[o] = la;
    } else {
        int i = (blk - 16896) * 256 + tid;
        if (i < 2048)      g_bias[i] = qb[i];
        else if (i < 2176) g_bias[i] = kb[i - 2048];
        else if (i < 2304) g_bias[i] = vb[i - 2176];
    }
}

// quantize O (bf16 hi+lo) -> s8 digits with tight scale QMAX/|O|max
__global__ __launch_bounds__(256) void quantO()
{
    int i = blockIdx.x * 256 + threadIdx.x;   // 4 elements each
    const float S = QMAX / __uint_as_float(g_amax[1]);
    uint2 hw = ((const uint2*)g_Oh)[i];
    uint2 lw = ((const uint2*)g_Ol)[i];
    float v[4];
    v[0] = __bfloat162float(__ushort_as_bfloat16((unsigned short)(hw.x & 0xffff)))
         + __bfloat162float(__ushort_as_bfloat16((unsigned short)(lw.x & 0xffff)));
    v[1] = __bfloat162float(__ushort_as_bfloat16((unsigned short)(hw.x >> 16)))
         + __bfloat162float(__ushort_as_bfloat16((unsigned short)(lw.x >> 16)));
    v[2] = __bfloat162float(__ushort_as_bfloat16((unsigned short)(hw.y & 0xffff)))
         + __bfloat162float(__ushort_as_bfloat16((unsigned short)(lw.y & 0xffff)));
    v[3] = __bfloat162float(__ushort_as_bfloat16((unsigned short)(hw.y >> 16)))
         + __bfloat162float(__ushort_as_bfloat16((unsigned short)(lw.y >> 16)));
    uint32_t ha = 0, la = 0;
#pragma unroll
    for (int r = 0; r < 4; r++) {
        int h, l;
        qdig(v[r], S, h, l);
        ha |= (uint32_t)(h & 0xff) << (8 * r);
        la |= (uint32_t)(l & 0xff) << (8 * r);
    }
    ((uint32_t*)g_Oa)[i] = ha;
    ((uint32_t*)g_Ob)[i] = la;
}

// ---------------------------------------------------------------------------
// bf16 GEMM machinery (R9): BM=128 BN=128 BK=32, 128 thr, 64x64 warp tiles.
// ---------------------------------------------------------------------------
#define STG_BYTES 32768
#define G2SMEM (3 * STG_BYTES)
#define NITER (KTOT / 32)
#define GTHR 128

__device__ __forceinline__ uint32_t a_off(int r, int c) {
    return (uint32_t)(r * 64 + ((c ^ ((r >> 1) & 3)) << 4));
}
__device__ __forceinline__ uint32_t b_off(int r, int c) {
    return (uint32_t)(r * 256 + ((c ^ (r & 7)) << 4));
}

__device__ __forceinline__ void g2s_issue(
    uint32_t stg, const bf16* __restrict__ Ah, const bf16* __restrict__ Al,
    const bf16* __restrict__ Wh, const bf16* __restrict__ Wl,
    int N, int m0, int n0, int k0, int tid)
{
#pragma unroll
    for (int p = 0; p < 4; p++) {
        int cid = p * GTHR + tid;
        int r = cid >> 2, c = cid & 3;
        size_t gs = (size_t)(m0 + r) * KTOT + k0 + c * 8;
        uint32_t off = a_off(r, c);
        CP16(stg + off, Ah + gs);
        CP16(stg + 8192 + off, Al + gs);
    }
#pragma unroll
    for (int p = 0; p < 4; p++) {
        int cid = p * GTHR + tid;
        int r = cid >> 4, c = cid & 15;
        size_t gs = (size_t)(k0 + r) * N + n0 + c * 8;
        uint32_t off = b_off(r, c);
        CP16(stg + 16384 + off, Wh + gs);
        CP16(stg + 24576 + off, Wl + gs);
    }
}

__device__ __forceinline__ void gemm_mainloop(
    uint32_t sb, const bf16* Ah, const bf16* Al, const bf16* Wh, const bf16* Wl,
    int N, int m0, int n0, int tid, int lane, int wm, int wn, float acc[4][8][4])
{
    const int lrow = lane & 15;
    const int lsel = lane >> 4;

    g2s_issue(sb, Ah, Al, Wh, Wl, N, m0, n0, 0, tid);
    CP_COMMIT();
    g2s_issue(sb + STG_BYTES, Ah, Al, Wh, Wl, N, m0, n0, 32, tid);
    CP_COMMIT();

    for (int it = 0; it < NITER; it++) {
        if (it == NITER - 1) CP_WAIT(0); else CP_WAIT(1);
        __syncthreads();
        if (it + 2 < NITER) {
            g2s_issue(sb + ((it + 2) % 3) * STG_BYTES, Ah, Al, Wh, Wl, N,
                      m0, n0, (it + 2) * 32, tid);
            CP_COMMIT();
        }

        const uint32_t stA = sb + (uint32_t)(it % 3) * STG_BYTES;
        const uint32_t stB = stA + 16384;

#pragma unroll
        for (int ks = 0; ks < 2; ks++) {
            uint32_t ah[4][4], al[4][4];
#pragma unroll
            for (int mf = 0; mf < 4; mf++) {
                int row = wm * 64 + mf * 16 + lrow;
                int chunk = ks * 2 + lsel;
                uint32_t addr = stA + a_off(row, chunk);
                LDSM_X4(ah[mf][0], ah[mf][1], ah[mf][2], ah[mf][3], addr);
                LDSM_X4(al[mf][0], al[mf][1], al[mf][2], al[mf][3], addr + 8192);
            }
#pragma unroll
            for (int nj = 0; nj < 4; nj++) {
                int brow = ks * 16 + lrow;
                int bchunk = wn * 8 + nj * 2 + lsel;
                uint32_t baddr = stB + b_off(brow, bchunk);
                uint32_t bh[4], bl[4];
                LDSM_X4_T(bh[0], bh[1], bh[2], bh[3], baddr);
                LDSM_X4_T(bl[0], bl[1], bl[2], bl[3], baddr + 8192);
#pragma unroll
                for (int mf = 0; mf < 4; mf++) {
                    MMA_BF16(acc[mf][2 * nj],     ah[mf], bh[0], bh[1]);
                    MMA_BF16(acc[mf][2 * nj + 1], ah[mf], bh[2], bh[3]);
                }
#pragma unroll
                for (int mf = 0; mf < 4; mf++) {
                    MMA_BF16(acc[mf][2 * nj],     ah[mf], bl[0], bl[1]);
                    MMA_BF16(acc[mf][2 * nj + 1], ah[mf], bl[2], bl[3]);
                }
#pragma unroll
                for (int mf = 0; mf < 4; mf++) {
                    MMA_BF16(acc[mf][2 * nj],     al[mf], bh[0], bh[1]);
                    MMA_BF16(acc[mf][2 * nj + 1], al[mf], bh[2], bh[3]);
                }
            }
        }
    }
}

// Fused QKV GEMM (R9 exact)
__global__ __launch_bounds__(GTHR, 2)
void gemm_qkv(const float* __restrict__ cs, const float* __restrict__ sn)
{
    extern __shared__ char sm[];
    const uint32_t sb = smem_u32(sm);
    const int tid  = threadIdx.x;
    const int lane = tid & 31;
    const int wid  = tid >> 5;
    const int wm   = wid >> 1;
    const int wn   = wid & 1;
    const int m0   = blockIdx.y * 128;
    const int n0   = blockIdx.x * 128;

    float acc[4][8][4];
#pragma unroll
    for (int i = 0; i < 4; i++)
#pragma unroll
        for (int j = 0; j < 8; j++)
#pragma unroll
            for (int q = 0; q < 4; q++) acc[i][j][q] = 0.f;

    gemm_mainloop(sb, g_xh, g_xl, g_wh, g_wl, NQKV, m0, n0, tid, lane, wm, wn, acc);

    const int g = lane >> 2, t = lane & 3;
#pragma unroll
    for (int mf = 0; mf < 4; mf++) {
        int row0 = m0 + wm * 64 + mf * 16 + g;
#pragma unroll
        for (int nt = 0; nt < 8; nt++) {
            int col = n0 + wn * 64 + nt * 8 + 2 * t;
            float2 bi = *(const float2*)(g_bias + col);
            float a0 = acc[mf][nt][0] + bi.x, a1 = acc[mf][nt][1] + bi.y;
            float a2 = acc[mf][nt][2] + bi.x, a3 = acc[mf][nt][3] + bi.y;
            if (col < 2048) {
                int f = (col & 127) >> 1;
#pragma unroll
                for (int rr = 0; rr < 2; rr++) {
                    int r = row0 + rr * 8;
                    int tloc = r & (TT - 1);
                    float c = cs[tloc * 64 + f], s = sn[tloc * 64 + f];
                    float re = rr ? a2 : a0, im = rr ? a3 : a1;
                    float ore = (re * c - im * s) * QSCALE;
                    float oim = (re * s + im * c) * QSCALE;
                    uint32_t hi, lo;
                    split2(ore, oim, hi, lo);
                    int bq = r >> 11, hq = col >> 7;
                    size_t idx = ((size_t)(bq * HH + hq) * TT + tloc) * DD + (col & 127);
                    *(uint32_t*)(g_Qh + idx) = hi;
                    *(uint32_t*)(g_Ql + idx) = lo;
                }
            } else if (col < 2176) {
                int colp = col - 2048;
                int f = colp >> 1;
#pragma unroll
                for (int rr = 0; rr < 2; rr++) {
                    int r = row0 + rr * 8;
                    int tloc = r & (TT - 1);
                    float c = cs[tloc * 64 + f], s = sn[tloc * 64 + f];
                    float re = rr ? a2 : a0, im = rr ? a3 : a1;
                    float ore = re * c - im * s;
                    float oim = re * s + im * c;
                    uint32_t hi, lo;
                    split2(ore, oim, hi, lo);
                    size_t idx = (size_t)r * DD + colp;
                    *(uint32_t*)(g_Kh + idx) = hi;
                    *(uint32_t*)(g_Kl + idx) = lo;
                }
            } else {
                int colp = col - 2176;
                uint32_t hi, lo;
                split2(a0, a1, hi, lo);
                *(uint32_t*)(g_Vh + (size_t)row0 * DD + colp) = hi;
                *(uint32_t*)(g_Vl + (size_t)row0 * DD + colp) = lo;
                split2(a2, a3, hi, lo);
                *(uint32_t*)(g_Vh + (size_t)(row0 + 8) * DD + colp) = hi;
                *(uint32_t*)(g_Vl + (size_t)(row0 + 8) * DD + colp) = lo;
            }
        }
    }
}

// ---------------------------------------------------------------------------
// int8 output GEMM: CTA 64x64 BK=32, 4 warps of 32x32, 4-term EXACT digits.
// Stage (8KB): Aa 2K | Ab 2K | Ba 2K | Bb 2K. 4 stages, 2 CTA/SM.
// ---------------------------------------------------------------------------
#define ISTG 8192
#define ISMEM (4 * ISTG)

__device__ __forceinline__ uint32_t soff(int r, int c) {
    return (uint32_t)((r >> 2) * 128 +
                      ((((r & 3) * 2) + (c ^ ((r >> 2) & 1))) << 4));
}

__device__ __forceinline__ void g2s_i8(uint32_t stg, int m0, int n0, int k0, int tid)
{
    int r = tid >> 1, c = tid & 1;
    size_t ga = (size_t)(m0 + r) * KTOT + k0 + c * 16;
    size_t gb = (size_t)(n0 + r) * KTOT + k0 + c * 16;
    uint32_t off = soff(r, c);
    CP16(stg + off, g_Oa + ga);
    CP16(stg + 2048 + off, g_Ob + ga);
    CP16(stg + 4096 + off, g_woTa + gb);
    CP16(stg + 6144 + off, g_woTb + gb);
}

__global__ __launch_bounds__(128, 2)
void gemm_out_i8(const float* __restrict__ bias, float* __restrict__ OutF)
{
    extern __shared__ char sm[];
    const uint32_t sb = smem_u32(sm);
    const int tid  = threadIdx.x;
    const int lane = tid & 31;
    const int wid  = tid >> 5;
    const int wm   = wid >> 1;
    const int wn   = wid & 1;
    const int m0   = blockIdx.y * 64;
    const int n0   = blockIdx.x * 64;
    const int lr   = lane & 15;
    const int ls   = lane >> 4;

    int hh[2][4][4], mid[2][4][4], ll[2][4][4];
#pragma unroll
    for (int i = 0; i < 2; i++)
#pragma unroll
        for (int j = 0; j < 4; j++)
#pragma unroll
            for (int q = 0; q < 4; q++) { hh[i][j][q] = 0; mid[i][j][q] = 0; ll[i][j][q] = 0; }

    g2s_i8(sb, m0, n0, 0, tid);             CP_COMMIT();
    g2s_i8(sb + ISTG, m0, n0, 32, tid);     CP_COMMIT();
    g2s_i8(sb + 2 * ISTG, m0, n0, 64, tid); CP_COMMIT();

    for (int it = 0; it < NITER; it++) {
        if (it + 2 < NITER)      CP_WAIT(2);
        else if (it + 1 < NITER) CP_WAIT(1);
        else                     CP_WAIT(0);
        __syncthreads();
        if (it + 3 < NITER) {
            g2s_i8(sb + ((it + 3) & 3) * ISTG, m0, n0, (it + 3) * 32, tid);
            CP_COMMIT();
        }

        const uint32_t stg = sb + (uint32_t)(it & 3) * ISTG;

        uint32_t aa[2][4], ab[2][4];
#pragma unroll
        for (int mf = 0; mf < 2; mf++) {
            uint32_t addr = stg + soff(wm * 32 + mf * 16 + lr, ls);
            LDSM_X4(aa[mf][0], aa[mf][1], aa[mf][2], aa[mf][3], addr);
            LDSM_X4(ab[mf][0], ab[mf][1], ab[mf][2], ab[mf][3], addr + 2048);
        }
#pragma unroll
        for (int pb = 0; pb < 2; pb++) {
            uint32_t baddr = stg + 4096 + soff(wn * 32 + pb * 16 + lr, ls);
            uint32_t ba[4], bb[4];
            LDSM_X4(ba[0], ba[1], ba[2], ba[3], baddr);
            LDSM_X4(bb[0], bb[1], bb[2], bb[3], baddr + 2048);
            int nf0 = pb * 2, nf1 = pb * 2 + 1;
#pragma unroll
            for (int mf = 0; mf < 2; mf++) {
                MMA_S8(hh[mf][nf0],  aa[mf], ba[0], ba[2]);
                MMA_S8(hh[mf][nf1],  aa[mf], ba[1], ba[3]);
                MMA_S8(mid[mf][nf0], aa[mf], bb[0], bb[2]);
                MMA_S8(mid[mf][nf1], aa[mf], bb[1], bb[3]);
                MMA_S8(mid[mf][nf0], ab[mf], ba[0], ba[2]);
                MMA_S8(mid[mf][nf1], ab[mf], ba[1], ba[3]);
                MMA_S8(ll[mf][nf0],  ab[mf], bb[0], bb[2]);
                MMA_S8(ll[mf][nf1],  ab[mf], bb[1], bb[3]);
            }
        }
    }

    const float invS = __uint_as_float(g_amax[1]) * __uint_as_float(g_amax[0])
                       / (QMAX * QMAX);
    const int g = lane >> 2, t = lane & 3;
#pragma unroll
    for (int mf = 0; mf < 2; mf++) {
        int row0 = m0 + wm * 32 + mf * 16 + g;
#pragma unroll
        for (int nf = 0; nf < 4; nf++) {
            int col = n0 + wn * 32 + nf * 8 + 2 * t;
            float2 bi = *(const float2*)(bias + col);
            float a0 = (65536.f * (float)hh[mf][nf][0] + 256.f * (float)mid[mf][nf][0]
                        + (float)ll[mf][nf][0]) * invS + bi.x;
            float a1 = (65536.f * (float)hh[mf][nf][1] + 256.f * (float)mid[mf][nf][1]
                        + (float)ll[mf][nf][1]) * invS + bi.y;
            float a2 = (65536.f * (float)hh[mf][nf][2] + 256.f * (float)mid[mf][nf][2]
                        + (float)ll[mf][nf][2]) * invS + bi.x;
            float a3 = (65536.f * (float)hh[mf][nf][3] + 256.f * (float)mid[mf][nf][3]
                        + (float)ll[mf][nf][3]) * invS + bi.y;
            *(float2*)(OutF + (size_t)row0 * CC + col)       = make_float2(a0, a1);
            *(float2*)(OutF + (size_t)(row0 + 8) * CC + col) = make_float2(a2, a3);
        }
    }
}

// ---------------------------------------------------------------------------
// Flash attention (R9) + |O| absmax; writes bf16 O hi/lo.
// ---------------------------------------------------------------------------
#define AQ_L 16384u
#define AKV(s) (32768u + (uint32_t)(s) * 32768u)
#define A_SMEM 98304

__device__ __forceinline__ uint32_t toff(int r, int c) {
    return (uint32_t)(r * 256 + ((c ^ (r & 7)) << 4));
}

__global__ __launch_bounds__(128, 2) void attn_mma()
{
    extern __shared__ char sm[];
    const uint32_t sb = smem_u32(sm);
    const int tid = threadIdx.x, lane = tid & 31, w = tid >> 5;
    const int id = blockIdx.x;
    const int bx = (TT / 64 - 1) - (id >> 5);
    const int hb = id & 31;
    const int h  = hb & 15;
    const int b  = hb >> 4;
    const int i0 = bx * 64;
    const int jtmax = 2 * bx + 1;

    const size_t qbase  = ((size_t)(b * HH + h) * TT + i0) * DD;
    const size_t kvbase = (size_t)b * TT * DD;

#pragma unroll
    for (int i = 0; i < 8; i++) {
        int cid = i * 128 + tid;
        int r = cid >> 4, c = cid & 15;
        size_t gs = qbase + (size_t)r * DD + c * 8;
        uint32_t off = toff(r, c);
        CP16(sb + off, g_Qh + gs);
        CP16(sb + AQ_L + off, g_Ql + gs);
    }
#pragma unroll
    for (int i = 0; i < 4; i++) {
        int cid = i * 128 + tid;
        int r = cid >> 4, c = cid & 15;
        size_t gs = kvbase + (size_t)r * DD + c * 8;
        uint32_t off = toff(r, c);
        CP16(sb + AKV(0) + off,          g_Kh + gs);
        CP16(sb + AKV(0) + 8192 + off,   g_Kl + gs);
        CP16(sb + AKV(0) + 16384 + off,  g_Vh + gs);
        CP16(sb + AKV(0) + 24576 + off,  g_Vl + gs);
    }
    CP_COMMIT();

    const int lrA = lane & 15;
    const int lsA = lane >> 4;
    const int lrB = (lane & 7) + ((lane >> 4) << 3);
    const int csB = (lane >> 3) & 1;
    const int g = lane >> 2, t = lane & 3;

    float oa[16][4];
#pragma unroll
    for (int i = 0; i < 16; i++)
#pragma unroll
        for (int j = 0; j < 4; j++) oa[i][j] = 0.f;
    float m0r = -1e30f, m1r = -1e30f, l0r = 0.f, l1r = 0.f;

    for (int jt = 0; jt <= jtmax; jt++) {
        if (jt > 0) __syncthreads();
        if (jt + 1 <= jtmax) {
            uint32_t stg = AKV((jt + 1) & 1);
#pragma unroll
            for (int i = 0; i < 4; i++) {
                int cid = i * 128 + tid;
                int r = cid >> 4, c = cid & 15;
                size_t gs = kvbase + (size_t)((jt + 1) * 32 + r) * DD + c * 8;
                uint32_t off = toff(r, c);
                CP16(sb + stg + off,          g_Kh + gs);
                CP16(sb + stg + 8192 + off,   g_Kl + gs);
                CP16(sb + stg + 16384 + off,  g_Vh + gs);
                CP16(sb + stg + 24576 + off,  g_Vl + gs);
            }
            CP_COMMIT();
            CP_WAIT(1);
        } else {
            CP_WAIT(0);
        }
        __syncthreads();

        if (32 * jt > i0 + 16 * w + 15) continue;

        const uint32_t kvs = sb + AKV(jt & 1);

        float sa[4][4];
#pragma unroll
        for (int i = 0; i < 4; i++)
#pragma unroll
            for (int j = 0; j < 4; j++) sa[i][j] = 0.f;

#pragma unroll
        for (int ks = 0; ks < 8; ks++) {
            uint32_t ah[4], al[4];
            uint32_t qaddr = sb + toff(16 * w + lrA, 2 * ks + lsA);
            LDSM_X4(ah[0], ah[1], ah[2], ah[3], qaddr);
            LDSM_X4(al[0], al[1], al[2], al[3], qaddr + AQ_L);

            uint32_t kh[2][4], kl[2][4];
#pragma unroll
            for (int np = 0; np < 2; np++) {
                uint32_t kaddr = kvs + toff(np * 16 + lrB, 2 * ks + csB);
                LDSM_X4(kh[np][0], kh[np][1], kh[np][2], kh[np][3], kaddr);
                LDSM_X4(kl[np][0], kl[np][1], kl[np][2], kl[np][3], kaddr + 8192);
            }
            MMA_BF16(sa[0], ah, kh[0][0], kh[0][1]);
            MMA_BF16(sa[1], ah, kh[0][2], kh[0][3]);
            MMA_BF16(sa[2], ah, kh[1][0], kh[1][1]);
            MMA_BF16(sa[3], ah, kh[1][2], kh[1][3]);

            MMA_BF16(sa[0], ah, kl[0][0], kl[0][1]);
            MMA_BF16(sa[1], ah, kl[0][2], kl[0][3]);
            MMA_BF16(sa[2], ah, kl[1][0], kl[1][1]);
            MMA_BF16(sa[3], ah, kl[1][2], kl[1][3]);

            MMA_BF16(sa[0], al, kh[0][0], kh[0][1]);
            MMA_BF16(sa[1], al, kh[0][2], kh[0][3]);
            MMA_BF16(sa[2], al, kh[1][0], kh[1][1]);
            MMA_BF16(sa[3], al, kh[1][2], kh[1][3]);
        }

        if (32 * jt + 31 > i0 + 16 * w) {
            int r0g = i0 + 16 * w + g;
#pragma unroll
            for (int nf = 0; nf < 4; nf++) {
                int cg = 32 * jt + nf * 8 + 2 * t;
                if (cg     > r0g)     sa[nf][0] = -1e30f;
                if (cg + 1 > r0g)     sa[nf][1] = -1e30f;
                if (cg     > r0g + 8) sa[nf][2] = -1e30f;
                if (cg + 1 > r0g + 8) sa[nf][3] = -1e30f;
            }
        }

        float mx0 = -1e30f, mx1 = -1e30f;
#pragma unroll
        for (int nf = 0; nf < 4; nf++) {
            mx0 = fmaxf(mx0, fmaxf(sa[nf][0], sa[nf][1]));
            mx1 = fmaxf(mx1, fmaxf(sa[nf][2], sa[nf][3]));
        }
        mx0 = fmaxf(mx0, __shfl_xor_sync(0xffffffffu, mx0, 1));
        mx0 = fmaxf(mx0, __shfl_xor_sync(0xffffffffu, mx0, 2));
        mx1 = fmaxf(mx1, __shfl_xor_sync(0xffffffffu, mx1, 1));
        mx1 = fmaxf(mx1, __shfl_xor_sync(0xffffffffu, mx1, 2));
        float mn0 = fmaxf(m0r, mx0), mn1 = fmaxf(m1r, mx1);

        float sum0 = 0.f, sum1 = 0.f;
#pragma unroll
        for (int nf = 0; nf < 4; nf++) {
            sa[nf][0] = ex2(sa[nf][0] - mn0);
            sa[nf][1] = ex2(sa[nf][1] - mn0);
            sa[nf][2] = ex2(sa[nf][2] - mn1);
            sa[nf][3] = ex2(sa[nf][3] - mn1);
            sum0 += sa[nf][0] + sa[nf][1];
            sum1 += sa[nf][2] + sa[nf][3];
        }
        sum0 += __shfl_xor_sync(0xffffffffu, sum0, 1);
        sum0 += __shfl_xor_sync(0xffffffffu, sum0, 2);
        sum1 += __shfl_xor_sync(0xffffffffu, sum1, 1);
        sum1 += __shfl_xor_sync(0xffffffffu, sum1, 2);

        float scl0 = ex2(m0r - mn0), scl1 = ex2(m1r - mn1);
        l0r = l0r * scl0 + sum0;
        l1r = l1r * scl1 + sum1;
        m0r = mn0; m1r = mn1;

#pragma unroll
        for (int nf = 0; nf < 16; nf++) {
            oa[nf][0] *= scl0; oa[nf][1] *= scl0;
            oa[nf][2] *= scl1; oa[nf][3] *= scl1;
        }

#pragma unroll
        for (int s = 0; s < 2; s++) {
            uint32_t aPh[4], aPl[4];
            split2(sa[2 * s][0],     sa[2 * s][1],     aPh[0], aPl[0]);
            split2(sa[2 * s][2],     sa[2 * s][3],     aPh[1], aPl[1]);
            split2(sa[2 * s + 1][0], sa[2 * s + 1][1], aPh[2], aPl[2]);
            split2(sa[2 * s + 1][2], sa[2 * s + 1][3], aPh[3], aPl[3]);
#pragma unroll
            for (int npp = 0; npp < 4; npp++) {
                int np0 = 2 * npp, np1 = 2 * npp + 1;
                uint32_t va0 = kvs + 16384 + toff(s * 16 + lrA, 2 * np0 + lsA);
                uint32_t va1 = kvs + 16384 + toff(s * 16 + lrA, 2 * np1 + lsA);
                uint32_t vh0[4], vl0[4], vh1[4], vl1[4];
                LDSM_X4_T(vh0[0], vh0[1], vh0[2], vh0[3], va0);
                LDSM_X4_T(vl0[0], vl0[1], vl0[2], vl0[3], va0 + 8192);
                LDSM_X4_T(vh1[0], vh1[1], vh1[2], vh1[3], va1);
                LDSM_X4_T(vl1[0], vl1[1], vl1[2], vl1[3], va1 + 8192);

                MMA_BF16(oa[2 * np0],     aPh, vh0[0], vh0[1]);
                MMA_BF16(oa[2 * np0 + 1], aPh, vh0[2], vh0[3]);
                MMA_BF16(oa[2 * np1],     aPh, vh1[0], vh1[1]);
                MMA_BF16(oa[2 * np1 + 1], aPh, vh1[2], vh1[3]);

                MMA_BF16(oa[2 * np0],     aPh, vl0[0], vl0[1]);
                MMA_BF16(oa[2 * np0 + 1], aPh, vl0[2], vl0[3]);
                MMA_BF16(oa[2 * np1],     aPh, vl1[0], vl1[1]);
                MMA_BF16(oa[2 * np1 + 1], aPh, vl1[2], vl1[3]);

                MMA_BF16(oa[2 * np0],     aPl, vh0[0], vh0[1]);
                MMA_BF16(oa[2 * np0 + 1], aPl, vh0[2], vh0[3]);
                MMA_BF16(oa[2 * np1],     aPl, vh1[0], vh1[1]);
                MMA_BF16(oa[2 * np1 + 1], aPl, vh1[2], vh1[3]);
            }
        }
    }

    // epilogue: write bf16 O hi/lo + track |O| max
    float inv0 = 1.f / l0r, inv1 = 1.f / l1r;
    float omax = 0.f;
    size_t or0 = (size_t)(b * TT + i0 + 16 * w + g) * CC + h * DD;
    size_t or1 = or0 + (size_t)8 * CC;
#pragma unroll
    for (int nf = 0; nf < 16; nf++) {
        int col = nf * 8 + 2 * t;
        float v0 = oa[nf][0] * inv0, v1 = oa[nf][1] * inv0;
        float v2 = oa[nf][2] * inv1, v3 = oa[nf][3] * inv1;
        omax = fmaxf(omax, fmaxf(fmaxf(fabsf(v0), fabsf(v1)),
                                 fmaxf(fabsf(v2), fabsf(v3))));
        uint32_t hi, lo;
        split2(v0, v1, hi, lo);
        *(uint32_t*)(g_Oh + or0 + col) = hi;
        *(uint32_t*)(g_Ol + or0 + col) = lo;
        split2(v2, v3, hi, lo);
        *(uint32_t*)(g_Oh + or1 + col) = hi;
        *(uint32_t*)(g_Ol + or1 + col) = lo;
    }
#pragma unroll
    for (int o = 16; o > 0; o >>= 1)
        omax = fmaxf(omax, __shfl_xor_sync(0xffffffffu, omax, o));
    if (lane == 0) atomicMax(&g_amax[1], __float_as_uint(omax));
}

// ---------------------------------------------------------------------------
extern "C" void kernel_launch(void* const* d_in, const int* in_sizes, int n_in,
                              void* d_out, int out_size)
{
    const float* x    = (const float*)d_in[0];
    const float* fcos = (const float*)d_in[1];
    const float* fsin = (const float*)d_in[2];
    const float* wq   = (const float*)d_in[4];
    const float* wqb  = (const float*)d_in[5];
    const float* wk   = (const float*)d_in[6];
    const float* wkb  = (const float*)d_in[7];
    const float* wv   = (const float*)d_in[8];
    const float* wvb  = (const float*)d_in[9];
    const float* wo   = (const float*)d_in[10];
    const float* wob  = (const float*)d_in[11];
    float* out = (float*)d_out;

    cudaFuncSetAttribute(gemm_qkv, cudaFuncAttributeMaxDynamicSharedMemorySize, G2SMEM);
    cudaFuncSetAttribute(gemm_out_i8, cudaFuncAttributeMaxDynamicSharedMemorySize, ISMEM);
    cudaFuncSetAttribute(attn_mma, cudaFuncAttributeMaxDynamicSharedMemorySize, A_SMEM);

    zero_amax<<<1, 32>>>();
    amax_wo<<<1024, 256>>>(wo);
    prep_kernel<<<16905, 256>>>(x, wq, wk, wv, wo, wqb, wkb, wvb);

    gemm_qkv<<<dim3(NQKV / 128, MTOT / 128), GTHR, G2SMEM>>>(fcos, fsin);

    attn_mma<<<1024, 128, A_SMEM>>>();

    quantO<<<8192, 256>>>();

    gemm_out_i8<<<dim3(CC / 64, MTOT / 64), 128, ISMEM>>>(wob, out);
}

// round 14
// speedup vs baseline: 4.5416x; 4.5416x over previous
#include <cuda_runtime.h>
#include <cuda_fp16.h>
#include <cstdint>

#define BB 2
#define TT 2048
#define CC 2048
#define HH 16
#define DD 128
#define MTOT (BB * TT)
#define KTOT CC
#define NQKV 2304
#define QSCALE (0.08838834764831845f * 1.44269504088896340f)  // 1/sqrt(128)*log2e

// ---------------------------------------------------------------------------
// Scratch (fp16 everywhere)
// ---------------------------------------------------------------------------
__device__ __half g_x[(size_t)MTOT * KTOT];       // [m][k]
__device__ __half g_w[(size_t)KTOT * NQKV];       // [k][n] packed wq|wk|wv
__device__ __half g_wo[(size_t)KTOT * CC];        // [k][n]
__device__ float  g_bias[NQKV];

__device__ __half g_Q[(size_t)MTOT * CC];         // [B,H,T,D]
__device__ __half g_K[(size_t)MTOT * DD];         // [B,T,D]
__device__ __half g_V[(size_t)MTOT * DD];         // [B,T,D]
__device__ __half g_O[(size_t)MTOT * CC];         // [B,T,H*D]

// ---------------------------------------------------------------------------
// PTX helpers
// ---------------------------------------------------------------------------
__device__ __forceinline__ uint32_t smem_u32(const void* p) {
    uint32_t a;
    asm("{ .reg .u64 t; cvta.to.shared.u64 t, %1; cvt.u32.u64 %0, t; }"
        : "=r"(a) : "l"(p));
    return a;
}
__device__ __forceinline__ float ex2(float x) {
    float y; asm("ex2.approx.ftz.f32 %0, %1;" : "=f"(y) : "f"(x)); return y;
}

#define LDSM_X4(r0, r1, r2, r3, addr) \
    asm volatile("ldmatrix.sync.aligned.m8n8.x4.shared.b16 {%0,%1,%2,%3}, [%4];" \
                 : "=r"(r0), "=r"(r1), "=r"(r2), "=r"(r3) : "r"(addr))
#define LDSM_X4_T(r0, r1, r2, r3, addr) \
    asm volatile("ldmatrix.sync.aligned.m8n8.x4.trans.shared.b16 {%0,%1,%2,%3}, [%4];" \
                 : "=r"(r0), "=r"(r1), "=r"(r2), "=r"(r3) : "r"(addr))

#define MMA_F16(d, a, b0v, b1v) \
    asm volatile("mma.sync.aligned.m16n8k16.row.col.f32.f16.f16.f32 " \
                 "{%0,%1,%2,%3}, {%4,%5,%6,%7}, {%8,%9}, {%0,%1,%2,%3};" \
                 : "+f"((d)[0]), "+f"((d)[1]), "+f"((d)[2]), "+f"((d)[3]) \
                 : "r"((a)[0]), "r"((a)[1]), "r"((a)[2]), "r"((a)[3]), \
                   "r"(b0v), "r"(b1v))

#define CP16(dst, src) \
    asm volatile("cp.async.cg.shared.global [%0], [%1], 16;" :: "r"(dst), "l"(src))
#define CP_COMMIT() asm volatile("cp.async.commit_group;" ::: "memory")
#define CP_WAIT(n)  asm volatile("cp.async.wait_group %0;" :: "n"(n) : "memory")

__device__ __forceinline__ uint32_t packh2(float x, float y) {
    __half2 h = __floats2half2_rn(x, y);
    return *(uint32_t*)&h;
}

// ---------------------------------------------------------------------------
// prep: fp32 -> fp16 converts + bias pack. Blocks:
// [0,8192) x | [8192,12288) wq | [12288,12544) wk | [12544,12800) wv |
// [12800,16896) wo | [16896,16905) bias
// ---------------------------------------------------------------------------
__global__ __launch_bounds__(256) void prep_kernel(
    const float* __restrict__ x,  const float* __restrict__ wq,
    const float* __restrict__ wk, const float* __restrict__ wv,
    const float* __restrict__ wo,
    const float* __restrict__ qb, const float* __restrict__ kb,
    const float* __restrict__ vb)
{
    int blk = blockIdx.x, tid = threadIdx.x;
    if (blk < 8192) {                     // x contiguous
        int i = blk * 256 + tid;
        float4 v = ((const float4*)x)[i];
        ((uint2*)g_x)[i] = make_uint2(packh2(v.x, v.y), packh2(v.z, v.w));
    } else if (blk < 12288) {             // wq -> cols 0..2047 of g_w
        int i = (blk - 8192) * 256 + tid;
        int row = i >> 9, col = (i << 2) & 2047;
        float4 v = ((const float4*)wq)[i];
        *(uint2*)(g_w + (size_t)row * NQKV + col) =
            make_uint2(packh2(v.x, v.y), packh2(v.z, v.w));
    } else if (blk < 12544) {             // wk -> cols 2048..2175
        int i = (blk - 12288) * 256 + tid;
        int row = i >> 5, col = (i << 2) & 127;
        float4 v = ((const float4*)wk)[i];
        *(uint2*)(g_w + (size_t)row * NQKV + 2048 + col) =
            make_uint2(packh2(v.x, v.y), packh2(v.z, v.w));
    } else if (blk < 12800) {             // wv -> cols 2176..2303
        int i = (blk - 12544) * 256 + tid;
        int row = i >> 5, col = (i << 2) & 127;
        float4 v = ((const float4*)wv)[i];
        *(uint2*)(g_w + (size_t)row * NQKV + 2176 + col) =
            make_uint2(packh2(v.x, v.y), packh2(v.z, v.w));
    } else if (blk < 16896) {             // wo contiguous
        int i = (blk - 12800) * 256 + tid;
        float4 v = ((const float4*)wo)[i];
        ((uint2*)g_wo)[i] = make_uint2(packh2(v.x, v.y), packh2(v.z, v.w));
    } else {                              // bias
        int i = (blk - 16896) * 256 + tid;
        if (i < 2048)      g_bias[i] = qb[i];
        else if (i < 2176) g_bias[i] = kb[i - 2048];
        else if (i < 2304) g_bias[i] = vb[i - 2176];
    }
}

// ---------------------------------------------------------------------------
// fp16 GEMM machinery: BM=128 BN=128 BK=32, 128 thr (4 warps, 64x64 tiles),
// cp.async 3-stage (16KB/stage = A 8K | B 8K), 2 CTA/SM.
// ---------------------------------------------------------------------------
#define STG_BYTES 16384
#define G2SMEM (3 * STG_BYTES)
#define NITER (KTOT / 32)
#define GTHR 128

__device__ __forceinline__ uint32_t a_off(int r, int c) {
    return (uint32_t)(r * 64 + ((c ^ ((r >> 1) & 3)) << 4));
}
__device__ __forceinline__ uint32_t b_off(int r, int c) {
    return (uint32_t)(r * 256 + ((c ^ (r & 7)) << 4));
}

__device__ __forceinline__ void g2s_issue(
    uint32_t stg, const __half* __restrict__ A, const __half* __restrict__ W,
    int N, int m0, int n0, int k0, int tid)
{
#pragma unroll
    for (int p = 0; p < 4; p++) {
        int cid = p * GTHR + tid;
        int r = cid >> 2, c = cid & 3;
        CP16(stg + a_off(r, c), A + (size_t)(m0 + r) * KTOT + k0 + c * 8);
    }
#pragma unroll
    for (int p = 0; p < 4; p++) {
        int cid = p * GTHR + tid;
        int r = cid >> 4, c = cid & 15;
        CP16(stg + 8192 + b_off(r, c), W + (size_t)(k0 + r) * N + n0 + c * 8);
    }
}

__device__ __forceinline__ void gemm_mainloop(
    uint32_t sb, const __half* A, const __half* W,
    int N, int m0, int n0, int tid, int lane, int wm, int wn, float acc[4][8][4])
{
    const int lrow = lane & 15;
    const int lsel = lane >> 4;

    g2s_issue(sb, A, W, N, m0, n0, 0, tid);
    CP_COMMIT();
    g2s_issue(sb + STG_BYTES, A, W, N, m0, n0, 32, tid);
    CP_COMMIT();

    for (int it = 0; it < NITER; it++) {
        if (it == NITER - 1) CP_WAIT(0); else CP_WAIT(1);
        __syncthreads();
        if (it + 2 < NITER) {
            g2s_issue(sb + ((it + 2) % 3) * STG_BYTES, A, W, N,
                      m0, n0, (it + 2) * 32, tid);
            CP_COMMIT();
        }

        const uint32_t stA = sb + (uint32_t)(it % 3) * STG_BYTES;
        const uint32_t stB = stA + 8192;

#pragma unroll
        for (int ks = 0; ks < 2; ks++) {
            uint32_t a[4][4];
#pragma unroll
            for (int mf = 0; mf < 4; mf++) {
                uint32_t addr = stA + a_off(wm * 64 + mf * 16 + lrow, ks * 2 + lsel);
                LDSM_X4(a[mf][0], a[mf][1], a[mf][2], a[mf][3], addr);
            }
#pragma unroll
            for (int nj = 0; nj < 4; nj++) {
                uint32_t baddr = stB + b_off(ks * 16 + lrow, wn * 8 + nj * 2 + lsel);
                uint32_t b[4];
                LDSM_X4_T(b[0], b[1], b[2], b[3], baddr);
#pragma unroll
                for (int mf = 0; mf < 4; mf++) {
                    MMA_F16(acc[mf][2 * nj],     a[mf], b[0], b[1]);
                    MMA_F16(acc[mf][2 * nj + 1], a[mf], b[2], b[3]);
                }
            }
        }
    }
}

// ---------------------------------------------------------------------------
// Fused QKV GEMM: x @ [wq|wk|wv] + bias (N=2304, 18 CTA cols x 128).
// ---------------------------------------------------------------------------
__global__ __launch_bounds__(GTHR, 2)
void gemm_qkv(const float* __restrict__ cs, const float* __restrict__ sn)
{
    extern __shared__ char sm[];
    const uint32_t sb = smem_u32(sm);
    const int tid  = threadIdx.x;
    const int lane = tid & 31;
    const int wid  = tid >> 5;
    const int wm   = wid >> 1;
    const int wn   = wid & 1;
    const int m0   = blockIdx.y * 128;
    const int n0   = blockIdx.x * 128;

    float acc[4][8][4];
#pragma unroll
    for (int i = 0; i < 4; i++)
#pragma unroll
        for (int j = 0; j < 8; j++)
#pragma unroll
            for (int q = 0; q < 4; q++) acc[i][j][q] = 0.f;

    gemm_mainloop(sb, g_x, g_w, NQKV, m0, n0, tid, lane, wm, wn, acc);

    const int g = lane >> 2, t = lane & 3;
#pragma unroll
    for (int mf = 0; mf < 4; mf++) {
        int row0 = m0 + wm * 64 + mf * 16 + g;
#pragma unroll
        for (int nt = 0; nt < 8; nt++) {
            int col = n0 + wn * 64 + nt * 8 + 2 * t;
            float2 bi = *(const float2*)(g_bias + col);
            float a0 = acc[mf][nt][0] + bi.x, a1 = acc[mf][nt][1] + bi.y;
            float a2 = acc[mf][nt][2] + bi.x, a3 = acc[mf][nt][3] + bi.y;
            if (col < 2048) {
                // Q: RoPE + scale -> fp16 [B,H,T,D]
                int f = (col & 127) >> 1;
#pragma unroll
                for (int rr = 0; rr < 2; rr++) {
                    int r = row0 + rr * 8;
                    int tloc = r & (TT - 1);
                    float c = cs[tloc * 64 + f], s = sn[tloc * 64 + f];
                    float re = rr ? a2 : a0, im = rr ? a3 : a1;
                    float ore = (re * c - im * s) * QSCALE;
                    float oim = (re * s + im * c) * QSCALE;
                    int bq = r >> 11, hq = col >> 7;
                    size_t idx = ((size_t)(bq * HH + hq) * TT + tloc) * DD + (col & 127);
                    *(uint32_t*)(g_Q + idx) = packh2(ore, oim);
                }
            } else if (col < 2176) {
                int colp = col - 2048;
                int f = colp >> 1;
#pragma unroll
                for (int rr = 0; rr < 2; rr++) {
                    int r = row0 + rr * 8;
                    int tloc = r & (TT - 1);
                    float c = cs[tloc * 64 + f], s = sn[tloc * 64 + f];
                    float re = rr ? a2 : a0, im = rr ? a3 : a1;
                    *(uint32_t*)(g_K + (size_t)r * DD + colp) =
                        packh2(re * c - im * s, re * s + im * c);
                }
            } else {
                int colp = col - 2176;
                *(uint32_t*)(g_V + (size_t)row0 * DD + colp)       = packh2(a0, a1);
                *(uint32_t*)(g_V + (size_t)(row0 + 8) * DD + colp) = packh2(a2, a3);
            }
        }
    }
}

// ---------------------------------------------------------------------------
// Output GEMM: out = O @ wo + bias (fp32 out, N=2048)
// ---------------------------------------------------------------------------
__global__ __launch_bounds__(GTHR, 2)
void gemm_out(const float* __restrict__ bias, float* __restrict__ OutF)
{
    extern __shared__ char sm[];
    const uint32_t sb = smem_u32(sm);
    const int tid  = threadIdx.x;
    const int lane = tid & 31;
    const int wid  = tid >> 5;
    const int wm   = wid >> 1;
    const int wn   = wid & 1;
    const int m0   = blockIdx.y * 128;
    const int n0   = blockIdx.x * 128;

    float acc[4][8][4];
#pragma unroll
    for (int i = 0; i < 4; i++)
#pragma unroll
        for (int j = 0; j < 8; j++)
#pragma unroll
            for (int q = 0; q < 4; q++) acc[i][j][q] = 0.f;

    gemm_mainloop(sb, g_O, g_wo, CC, m0, n0, tid, lane, wm, wn, acc);

    const int g = lane >> 2, t = lane & 3;
#pragma unroll
    for (int mf = 0; mf < 4; mf++) {
        int row0 = m0 + wm * 64 + mf * 16 + g;
#pragma unroll
        for (int nt = 0; nt < 8; nt++) {
            int col = n0 + wn * 64 + nt * 8 + 2 * t;
            float2 bi = *(const float2*)(bias + col);
            *(float2*)(OutF + (size_t)row0 * CC + col) =
                make_float2(acc[mf][nt][0] + bi.x, acc[mf][nt][1] + bi.y);
            *(float2*)(OutF + (size_t)(row0 + 8) * CC + col) =
                make_float2(acc[mf][nt][2] + bi.x, acc[mf][nt][3] + bi.y);
        }
    }
}

// ---------------------------------------------------------------------------
// Flash attention fp16: BM=64 (4 warps x 16 rows), BN=32, D=128.
// smem 48KB: Q 16K | stage s (16K): K 8K, V 8K. base-2 softmax, heavy-first.
// ---------------------------------------------------------------------------
#define AKV(s) (16384u + (uint32_t)(s) * 16384u)
#define A_SMEM 49152

__device__ __forceinline__ uint32_t toff(int r, int c) {
    return (uint32_t)(r * 256 + ((c ^ (r & 7)) << 4));
}

__global__ __launch_bounds__(128, 3) void attn_mma()
{
    extern __shared__ char sm[];
    const uint32_t sb = smem_u32(sm);
    const int tid = threadIdx.x, lane = tid & 31, w = tid >> 5;
    const int id = blockIdx.x;
    const int bx = (TT / 64 - 1) - (id >> 5);
    const int hb = id & 31;
    const int h  = hb & 15;
    const int b  = hb >> 4;
    const int i0 = bx * 64;
    const int jtmax = 2 * bx + 1;

    const size_t qbase  = ((size_t)(b * HH + h) * TT + i0) * DD;
    const size_t kvbase = (size_t)b * TT * DD;

    // Q tile (64 rows x 128 fp16) + KV stage 0 (32 rows)
#pragma unroll
    for (int i = 0; i < 8; i++) {
        int cid = i * 128 + tid;
        int r = cid >> 4, c = cid & 15;
        CP16(sb + toff(r, c), g_Q + qbase + (size_t)r * DD + c * 8);
    }
#pragma unroll
    for (int i = 0; i < 4; i++) {
        int cid = i * 128 + tid;
        int r = cid >> 4, c = cid & 15;
        size_t gs = kvbase + (size_t)r * DD + c * 8;
        uint32_t off = toff(r, c);
        CP16(sb + AKV(0) + off,        g_K + gs);
        CP16(sb + AKV(0) + 8192 + off, g_V + gs);
    }
    CP_COMMIT();

    const int lrA = lane & 15;
    const int lsA = lane >> 4;
    const int lrB = (lane & 7) + ((lane >> 4) << 3);
    const int csB = (lane >> 3) & 1;
    const int g = lane >> 2, t = lane & 3;

    float oa[16][4];
#pragma unroll
    for (int i = 0; i < 16; i++)
#pragma unroll
        for (int j = 0; j < 4; j++) oa[i][j] = 0.f;
    float m0r = -1e30f, m1r = -1e30f, l0r = 0.f, l1r = 0.f;

    for (int jt = 0; jt <= jtmax; jt++) {
        if (jt > 0) __syncthreads();
        if (jt + 1 <= jtmax) {
            uint32_t stg = AKV((jt + 1) & 1);
#pragma unroll
            for (int i = 0; i < 4; i++) {
                int cid = i * 128 + tid;
                int r = cid >> 4, c = cid & 15;
                size_t gs = kvbase + (size_t)((jt + 1) * 32 + r) * DD + c * 8;
                uint32_t off = toff(r, c);
                CP16(sb + stg + off,        g_K + gs);
                CP16(sb + stg + 8192 + off, g_V + gs);
            }
            CP_COMMIT();
            CP_WAIT(1);
        } else {
            CP_WAIT(0);
        }
        __syncthreads();

        if (32 * jt > i0 + 16 * w + 15) continue;

        const uint32_t kvs = sb + AKV(jt & 1);

        // ---- S = Q K^T ----
        float sa[4][4];
#pragma unroll
        for (int i = 0; i < 4; i++)
#pragma unroll
            for (int j = 0; j < 4; j++) sa[i][j] = 0.f;

#pragma unroll
        for (int ks = 0; ks < 8; ks++) {
            uint32_t a[4];
            LDSM_X4(a[0], a[1], a[2], a[3],
                    sb + toff(16 * w + lrA, 2 * ks + lsA));
#pragma unroll
            for (int np = 0; np < 2; np++) {
                uint32_t k[4];
                LDSM_X4(k[0], k[1], k[2], k[3],
                        kvs + toff(np * 16 + lrB, 2 * ks + csB));
                MMA_F16(sa[2 * np],     a, k[0], k[1]);
                MMA_F16(sa[2 * np + 1], a, k[2], k[3]);
            }
        }

        // ---- causal mask ----
        if (32 * jt + 31 > i0 + 16 * w) {
            int r0g = i0 + 16 * w + g;
#pragma unroll
            for (int nf = 0; nf < 4; nf++) {
                int cg = 32 * jt + nf * 8 + 2 * t;
                if (cg     > r0g)     sa[nf][0] = -1e30f;
                if (cg + 1 > r0g)     sa[nf][1] = -1e30f;
                if (cg     > r0g + 8) sa[nf][2] = -1e30f;
                if (cg + 1 > r0g + 8) sa[nf][3] = -1e30f;
            }
        }

        // ---- online softmax (base-2) ----
        float mx0 = -1e30f, mx1 = -1e30f;
#pragma unroll
        for (int nf = 0; nf < 4; nf++) {
            mx0 = fmaxf(mx0, fmaxf(sa[nf][0], sa[nf][1]));
            mx1 = fmaxf(mx1, fmaxf(sa[nf][2], sa[nf][3]));
        }
        mx0 = fmaxf(mx0, __shfl_xor_sync(0xffffffffu, mx0, 1));
        mx0 = fmaxf(mx0, __shfl_xor_sync(0xffffffffu, mx0, 2));
        mx1 = fmaxf(mx1, __shfl_xor_sync(0xffffffffu, mx1, 1));
        mx1 = fmaxf(mx1, __shfl_xor_sync(0xffffffffu, mx1, 2));
        float mn0 = fmaxf(m0r, mx0), mn1 = fmaxf(m1r, mx1);

        float sum0 = 0.f, sum1 = 0.f;
#pragma unroll
        for (int nf = 0; nf < 4; nf++) {
            sa[nf][0] = ex2(sa[nf][0] - mn0);
            sa[nf][1] = ex2(sa[nf][1] - mn0);
            sa[nf][2] = ex2(sa[nf][2] - mn1);
            sa[nf][3] = ex2(sa[nf][3] - mn1);
            sum0 += sa[nf][0] + sa[nf][1];
            sum1 += sa[nf][2] + sa[nf][3];
        }
        sum0 += __shfl_xor_sync(0xffffffffu, sum0, 1);
        sum0 += __shfl_xor_sync(0xffffffffu, sum0, 2);
        sum1 += __shfl_xor_sync(0xffffffffu, sum1, 1);
        sum1 += __shfl_xor_sync(0xffffffffu, sum1, 2);

        float scl0 = ex2(m0r - mn0), scl1 = ex2(m1r - mn1);
        l0r = l0r * scl0 + sum0;
        l1r = l1r * scl1 + sum1;
        m0r = mn0; m1r = mn1;

#pragma unroll
        for (int nf = 0; nf < 16; nf++) {
            oa[nf][0] *= scl0; oa[nf][1] *= scl0;
            oa[nf][2] *= scl1; oa[nf][3] *= scl1;
        }

        // ---- O += P V ----
#pragma unroll
        for (int s = 0; s < 2; s++) {
            uint32_t aP[4];
            aP[0] = packh2(sa[2 * s][0],     sa[2 * s][1]);
            aP[1] = packh2(sa[2 * s][2],     sa[2 * s][3]);
            aP[2] = packh2(sa[2 * s + 1][0], sa[2 * s + 1][1]);
            aP[3] = packh2(sa[2 * s + 1][2], sa[2 * s + 1][3]);
#pragma unroll
            for (int np = 0; np < 8; np++) {
                uint32_t v[4];
                LDSM_X4_T(v[0], v[1], v[2], v[3],
                          kvs + 8192 + toff(s * 16 + lrA, 2 * np + lsA));
                MMA_F16(oa[2 * np],     aP, v[0], v[1]);
                MMA_F16(oa[2 * np + 1], aP, v[2], v[3]);
            }
        }
    }

    // ---- epilogue: normalize, write fp16 O [B,T,H*D] ----
    float inv0 = 1.f / l0r, inv1 = 1.f / l1r;
    size_t or0 = (size_t)(b * TT + i0 + 16 * w + g) * CC + h * DD;
    size_t or1 = or0 + (size_t)8 * CC;
#pragma unroll
    for (int nf = 0; nf < 16; nf++) {
        int col = nf * 8 + 2 * t;
        *(uint32_t*)(g_O + or0 + col) = packh2(oa[nf][0] * inv0, oa[nf][1] * inv0);
        *(uint32_t*)(g_O + or1 + col) = packh2(oa[nf][2] * inv1, oa[nf][3] * inv1);
    }
}

// ---------------------------------------------------------------------------
extern "C" void kernel_launch(void* const* d_in, const int* in_sizes, int n_in,
                              void* d_out, int out_size)
{
    const float* x    = (const float*)d_in[0];
    const float* fcos = (const float*)d_in[1];
    const float* fsin = (const float*)d_in[2];
    const float* wq   = (const float*)d_in[4];
    const float* wqb  = (const float*)d_in[5];
    const float* wk   = (const float*)d_in[6];
    const float* wkb  = (const float*)d_in[7];
    const float* wv   = (const float*)d_in[8];
    const float* wvb  = (const float*)d_in[9];
    const float* wo   = (const float*)d_in[10];
    const float* wob  = (const float*)d_in[11];
    float* out = (float*)d_out;

    cudaFuncSetAttribute(gemm_qkv, cudaFuncAttributeMaxDynamicSharedMemorySize, G2SMEM);
    cudaFuncSetAttribute(gemm_out, cudaFuncAttributeMaxDynamicSharedMemorySize, G2SMEM);
    cudaFuncSetAttribute(attn_mma, cudaFuncAttributeMaxDynamicSharedMemorySize, A_SMEM);

    // 1. fp32 -> fp16 converts + bias pack
    prep_kernel<<<16905, 256>>>(x, wq, wk, wv, wo, wqb, wkb, wvb);

    // 2. fused QKV projection
    gemm_qkv<<<dim3(NQKV / 128, MTOT / 128), GTHR, G2SMEM>>>(fcos, fsin);

    // 3. flash attention (fp16, 3 CTAs/SM, heavy-first)
    attn_mma<<<1024, 128, A_SMEM>>>();

    // 4. output projection -> d_out
    gemm_out<<<dim3(CC / 128, MTOT / 128), GTHR, G2SMEM>>>(wob, out);
}